// round 4
// baseline (speedup 1.0000x reference)
#include <cuda_runtime.h>
#include <math.h>
#include <stdint.h>

// GIN Grapher layer: enc+BN -> GINConv(scatter-add + MLP) -> FFN(2D) -> +x -> FFN(4D)
// fp32 SIMT, BN stats fused into GEMM epilogue, BN+GELU fused into GEMM prologue.
// Scratch in __device__ globals (no allocation, graph-capturable).

#define MAXN   50048            // padded capacity for N=50000
#define DIM    128

// ---------------- scratch ----------------
__device__ float g_Z  [(size_t)MAXN * 512];   // raw GEMM outputs (widest = 4D = 512)
__device__ float g_T  [(size_t)MAXN * DIM];   // narrow GEMM outputs needing standalone BN
__device__ float g_h0 [(size_t)MAXN * DIM];   // bn(enc(x))
__device__ float g_agg[(size_t)MAXN * DIM];   // h0 + scatter_add(h0)
__device__ float g_h1 [(size_t)MAXN * DIM];   // GIN MLP output
__device__ float g_h4 [(size_t)MAXN * DIM];   // after fc2 FFN + outer residual
__device__ float g_colsum[512];               // column-stat accumulators
__device__ float g_colsqs[512];
__device__ float g_sc[512];                   // BN folded scale  = gamma * rstd
__device__ float g_sh[512];                   // BN folded shift  = beta - mean*gamma*rstd

__device__ __forceinline__ float gelu_exact(float v) {
    return 0.5f * v * (1.f + erff(v * 0.70710678118654752f));
}

// ---------------- fused GEMM ----------------
// C[M,Nc] = op(A)[M,K] @ W[K,Nc] + bias
//   preBN   : op(A) = gelu(g_sc[k]*A[,k] + g_sh[k])
//   statsOut: accumulate column sum / sumsq of C into g_colsum/g_colsqs
// 128x128 block tile, BK=16, 256 threads, 8x8 outputs/thread (2x2 quadrants of 4).
__global__ __launch_bounds__(256)
void gemm_fused_kernel(const float* __restrict__ A, const float* __restrict__ W,
                       const float* __restrict__ bias, float* __restrict__ C,
                       int M, int K, int Nc, int preBN, int statsOut)
{
    __shared__ float As[16][132];  // [k][row]
    __shared__ float Ws[16][132];  // [k][col]

    const int tid  = threadIdx.x;
    const int row0 = blockIdx.y * 128;
    const int col0 = blockIdx.x * 128;

    const int ty = tid >> 4;        // 0..15
    const int tx = tid & 15;        // 0..15
    const int tr0 = ty << 2;        // rows tr0..tr0+3 and tr0+64..tr0+67
    const int tc0 = tx << 2;        // cols tc0..tc0+3 and tc0+64..tc0+67

    // A tile: 128 rows x 16 k -> 8 floats/thread
    const int aRow = tid >> 1;          // 0..127
    const int aCol = (tid & 1) << 3;    // 0 or 8
    // W tile: 16 k x 128 cols -> 8 floats/thread
    const int wRow = tid >> 4;          // 0..15
    const int wCol = (tid & 15) << 3;   // 0..120

    const bool aV = (row0 + aRow) < M;
    const float* Aptr = A + (size_t)(row0 + aRow) * K + aCol;
    const float* Wptr = W + (size_t)wRow * Nc + col0 + wCol;

    float acc[8][8];
    #pragma unroll
    for (int i = 0; i < 8; i++)
        #pragma unroll
        for (int j = 0; j < 8; j++) acc[i][j] = 0.f;

    for (int k0 = 0; k0 < K; k0 += 16) {
        float av[8] = {0.f, 0.f, 0.f, 0.f, 0.f, 0.f, 0.f, 0.f};
        if (aV) {
            float4 av0 = *(const float4*)(Aptr + k0);
            float4 av1 = *(const float4*)(Aptr + k0 + 4);
            av[0] = av0.x; av[1] = av0.y; av[2] = av0.z; av[3] = av0.w;
            av[4] = av1.x; av[5] = av1.y; av[6] = av1.z; av[7] = av1.w;
            if (preBN) {
                const int kk = k0 + aCol;
                #pragma unroll
                for (int j = 0; j < 8; j++) {
                    float v = fmaf(g_sc[kk + j], av[j], g_sh[kk + j]);
                    av[j] = gelu_exact(v);
                }
            }
        }
        float4 wv0 = *(const float4*)(Wptr + (size_t)k0 * Nc);
        float4 wv1 = *(const float4*)(Wptr + (size_t)k0 * Nc + 4);

        __syncthreads();
        #pragma unroll
        for (int j = 0; j < 8; j++) As[aCol + j][aRow] = av[j];
        *(float4*)&Ws[wRow][wCol]     = wv0;
        *(float4*)&Ws[wRow][wCol + 4] = wv1;
        __syncthreads();

        #pragma unroll
        for (int k = 0; k < 16; k++) {
            float4 a0 = *(const float4*)&As[k][tr0];
            float4 a1 = *(const float4*)&As[k][tr0 + 64];
            float4 b0 = *(const float4*)&Ws[k][tc0];
            float4 b1 = *(const float4*)&Ws[k][tc0 + 64];
            float ar[8] = {a0.x, a0.y, a0.z, a0.w, a1.x, a1.y, a1.z, a1.w};
            float br[8] = {b0.x, b0.y, b0.z, b0.w, b1.x, b1.y, b1.z, b1.w};
            #pragma unroll
            for (int i = 0; i < 8; i++)
                #pragma unroll
                for (int j = 0; j < 8; j++)
                    acc[i][j] += ar[i] * br[j];
        }
    }

    // bias
    {
        float4 bv0 = *(const float4*)(bias + col0 + tc0);
        float4 bv1 = *(const float4*)(bias + col0 + tc0 + 64);
        float bb[8] = {bv0.x, bv0.y, bv0.z, bv0.w, bv1.x, bv1.y, bv1.z, bv1.w};
        #pragma unroll
        for (int i = 0; i < 8; i++)
            #pragma unroll
            for (int j = 0; j < 8; j++) acc[i][j] += bb[j];
    }

    // store
    #pragma unroll
    for (int i = 0; i < 8; i++) {
        int r = row0 + tr0 + (i < 4 ? i : 60 + i);   // tr0+i or tr0+64+(i-4)
        if (r < M) {
            float* Crow = C + (size_t)r * Nc + col0;
            *(float4*)(Crow + tc0)      = make_float4(acc[i][0], acc[i][1], acc[i][2], acc[i][3]);
            *(float4*)(Crow + tc0 + 64) = make_float4(acc[i][4], acc[i][5], acc[i][6], acc[i][7]);
        }
    }

    // fused column stats (masked to valid rows)
    if (statsOut) {
        float s[8] = {0,0,0,0,0,0,0,0};
        float q[8] = {0,0,0,0,0,0,0,0};
        #pragma unroll
        for (int i = 0; i < 8; i++) {
            int r = row0 + tr0 + (i < 4 ? i : 60 + i);
            if (r < M) {
                #pragma unroll
                for (int j = 0; j < 8; j++) {
                    float v = acc[i][j];
                    s[j] += v;
                    q[j] += v * v;
                }
            }
        }
        __syncthreads();                 // done with As/Ws compute reads
        float* redS = &As[0][0];         // 16 groups x 128 cols (As: 2112 floats)
        float* redQ = &Ws[0][0];
        #pragma unroll
        for (int j = 0; j < 8; j++) {
            int cc = (j < 4) ? (tc0 + j) : (tc0 + 60 + j);
            redS[ty * 128 + cc] = s[j];
            redQ[ty * 128 + cc] = q[j];
        }
        __syncthreads();
        if (tid < 128) {
            float ts = 0.f, tq = 0.f;
            #pragma unroll
            for (int g2 = 0; g2 < 16; g2++) {
                ts += redS[g2 * 128 + tid];
                tq += redQ[g2 * 128 + tid];
            }
            atomicAdd(&g_colsum[col0 + tid], ts);
            atomicAdd(&g_colsqs[col0 + tid], tq);
        }
    }
}

// ---------------- finalize: fold BN params, re-zero accumulators ----------------
// launch <<<1,512>>>; Nc=0 acts as a pure zeroing pass.
__global__ void bn_finalize_kernel(int M, int Nc,
                                   const float* __restrict__ gamma,
                                   const float* __restrict__ beta)
{
    int c = threadIdx.x;
    if (c < Nc) {
        float s = g_colsum[c], q = g_colsqs[c];
        float m = s / (float)M;
        float v = q / (float)M - m * m;
        float rs = rsqrtf(v + 1e-5f);
        float sc = gamma[c] * rs;
        g_sc[c] = sc;
        g_sh[c] = beta[c] - m * sc;
    }
    g_colsum[c] = 0.f;
    g_colsqs[c] = 0.f;
}

// ---------------- standalone BN apply (+ residuals, dual output) ----------------
__global__ void bn_apply_kernel(const float* __restrict__ Z,
                                const float* __restrict__ r1,
                                const float* __restrict__ r2,
                                float* __restrict__ out,
                                float* __restrict__ out2,
                                int M, int Nc)
{
    size_t idx = ((size_t)blockIdx.x * blockDim.x + threadIdx.x) * 4;
    if (idx >= (size_t)M * Nc) return;
    int c = (int)(idx % (size_t)Nc);

    float4 z = *(const float4*)(Z + idx);
    float o[4] = {
        fmaf(g_sc[c + 0], z.x, g_sh[c + 0]),
        fmaf(g_sc[c + 1], z.y, g_sh[c + 1]),
        fmaf(g_sc[c + 2], z.z, g_sh[c + 2]),
        fmaf(g_sc[c + 3], z.w, g_sh[c + 3])
    };
    if (r1) {
        float4 a = *(const float4*)(r1 + idx);
        o[0] += a.x; o[1] += a.y; o[2] += a.z; o[3] += a.w;
    }
    if (r2) {
        float4 a = *(const float4*)(r2 + idx);
        o[0] += a.x; o[1] += a.y; o[2] += a.z; o[3] += a.w;
    }
    float4 ov = make_float4(o[0], o[1], o[2], o[3]);
    *(float4*)(out + idx) = ov;
    if (out2) *(float4*)(out2 + idx) = ov;
}

// ---------------- edge scatter-add: agg[dst] += h0[src] ----------------
__global__ void scatter_add_kernel(const float* __restrict__ H,
                                   const int* __restrict__ src,
                                   const int* __restrict__ dst,
                                   float* __restrict__ agg, int E)
{
    int e = blockIdx.x * 8 + threadIdx.y;
    if (e >= E) return;
    int s = src[e], d = dst[e];
    const float* hs = H + (size_t)s * DIM;
    float* ad = agg + (size_t)d * DIM;
    int l = threadIdx.x;
    #pragma unroll
    for (int j = 0; j < 4; j++) {
        atomicAdd(ad + l + j * 32, __ldg(hs + l + j * 32));
    }
}

// ---------------- host orchestration ----------------
extern "C" void kernel_launch(void* const* d_in, const int* in_sizes, int n_in,
                              void* d_out, int out_size)
{
    const float* x     = (const float*)d_in[0];
    const int*   ei    = (const int*)  d_in[1];
    const float* encW  = (const float*)d_in[2];
    const float* encb  = (const float*)d_in[3];
    const float* bng   = (const float*)d_in[4];
    const float* bnb   = (const float*)d_in[5];
    const float* gW1   = (const float*)d_in[6];
    const float* gb1   = (const float*)d_in[7];
    const float* gg    = (const float*)d_in[8];
    const float* gbb   = (const float*)d_in[9];
    const float* gW2   = (const float*)d_in[10];
    const float* gb2   = (const float*)d_in[11];
    const float* f2W1  = (const float*)d_in[12];
    const float* f2b1  = (const float*)d_in[13];
    const float* f2g1  = (const float*)d_in[14];
    const float* f2bb1 = (const float*)d_in[15];
    const float* f2W2  = (const float*)d_in[16];
    const float* f2b2  = (const float*)d_in[17];
    const float* f2g2  = (const float*)d_in[18];
    const float* f2bb2 = (const float*)d_in[19];
    const float* fnW1  = (const float*)d_in[20];
    const float* fnb1  = (const float*)d_in[21];
    const float* fng1  = (const float*)d_in[22];
    const float* fnbb1 = (const float*)d_in[23];
    const float* fnW2  = (const float*)d_in[24];
    const float* fnb2  = (const float*)d_in[25];
    const float* fng2  = (const float*)d_in[26];
    const float* fnbb2 = (const float*)d_in[27];

    const int M = in_sizes[0] / DIM;
    const int E = in_sizes[1] / 2;

    float *Z, *T, *h0, *agg, *h1, *h4;
    cudaGetSymbolAddress((void**)&Z,   g_Z);
    cudaGetSymbolAddress((void**)&T,   g_T);
    cudaGetSymbolAddress((void**)&h0,  g_h0);
    cudaGetSymbolAddress((void**)&agg, g_agg);
    cudaGetSymbolAddress((void**)&h1,  g_h1);
    cudaGetSymbolAddress((void**)&h4,  g_h4);

    const int gy = (M + 127) / 128;

    auto gemm = [&](const float* A, const float* W, const float* b, float* C,
                    int K, int Nc, int preBN, int statsOut) {
        dim3 grid(Nc / 128, gy);
        gemm_fused_kernel<<<grid, 256>>>(A, W, b, C, M, K, Nc, preBN, statsOut);
    };
    auto finalize = [&](int Nc, const float* ga, const float* be) {
        bn_finalize_kernel<<<1, 512>>>(M, Nc, ga, be);
    };
    auto bn = [&](const float* Zp, const float* r1, const float* r2,
                  float* o, float* o2, int Nc) {
        size_t tot = (size_t)M * Nc / 4;
        bn_apply_kernel<<<(unsigned)((tot + 255) / 256), 256>>>(Zp, r1, r2, o, o2, M, Nc);
    };

    // 0) zero stats accumulators (replay-safe)
    finalize(0, encb, encb);

    // 1) Z = x @ encW + encb   (stats fused)  -> h0 = BN(Z), agg = h0
    gemm(x, encW, encb, Z, DIM, DIM, 0, 1);
    finalize(DIM, bng, bnb);
    bn(Z, nullptr, nullptr, h0, agg, DIM);

    // 2) agg[dst] += h0[src]
    {
        dim3 blk(32, 8);
        scatter_add_kernel<<<(E + 7) / 8, blk>>>(h0, ei, ei + E, agg, E);
    }

    // 3) GIN MLP: Z = agg @ gW1 + gb1 (stats); h1 = gelu(BN(Z)) @ gW2 + gb2 (prologue-fused)
    gemm(agg, gW1, gb1, Z, DIM, DIM, 0, 1);
    finalize(DIM, gg, gbb);
    gemm(Z, gW2, gb2, h1, DIM, DIM, 1, 0);

    // 4) fc2 FFN: Z = h1 @ f2W1 + f2b1 (stats); T = gelu(BN(Z)) @ f2W2 + f2b2 (fused, stats)
    gemm(h1, f2W1, f2b1, Z, DIM, 2 * DIM, 0, 1);
    finalize(2 * DIM, f2g1, f2bb1);
    gemm(Z, f2W2, f2b2, T, 2 * DIM, DIM, 1, 1);
    finalize(DIM, f2g2, f2bb2);
    bn(T, h1, x, h4, nullptr, DIM);           // h4 = BN(T) + h1 (ffn residual) + x (outer)

    // 5) final FFN: Z = h4 @ fnW1 + fnb1 (stats); T = gelu(BN(Z)) @ fnW2 + fnb2 (fused, stats)
    gemm(h4, fnW1, fnb1, Z, DIM, 4 * DIM, 0, 1);
    finalize(4 * DIM, fng1, fnbb1);
    gemm(Z, fnW2, fnb2, T, 4 * DIM, DIM, 1, 1);
    finalize(DIM, fng2, fnbb2);
    bn(T, h4, nullptr, (float*)d_out, nullptr, DIM);  // out = BN(T) + h4
}

// round 9
// speedup vs baseline: 1.4175x; 1.4175x over previous
#include <cuda_runtime.h>
#include <cuda_bf16.h>
#include <math.h>
#include <stdint.h>

// GIN Grapher layer: enc+BN -> GINConv(scatter-add + MLP) -> FFN(2D) -> +x -> FFN(4D)
// GEMMs via bf16x3 emulated-fp32 on HMMA (mma.sync.m16n8k16), BN stats fused into
// GEMM epilogue, BN+GELU fused into GEMM prologue. Scratch in __device__ globals.

#define MAXN   50048
#define DIM    128

// ---------------- scratch ----------------
__device__ float g_Z  [(size_t)MAXN * 512];   // raw GEMM outputs (widest = 4D = 512)
__device__ float g_T  [(size_t)MAXN * DIM];
__device__ float g_h0 [(size_t)MAXN * DIM];
__device__ float g_agg[(size_t)MAXN * DIM];
__device__ float g_h1 [(size_t)MAXN * DIM];
__device__ float g_h4 [(size_t)MAXN * DIM];
__device__ float g_colsum[512];
__device__ float g_colsqs[512];
__device__ float g_sc[512];                   // BN folded scale = gamma * rstd
__device__ float g_sh[512];                   // BN folded shift = beta - mean*scale
// weight hi/lo splits, transposed to [n][k]; 262144 elements cover all 7 weights
__device__ __nv_bfloat16 g_Wh[262144];
__device__ __nv_bfloat16 g_Wl[262144];

__device__ __forceinline__ float gelu_exact(float v) {
    return 0.5f * v * (1.f + erff(v * 0.70710678118654752f));
}

__device__ __forceinline__ void mma_bf16(float* c, const unsigned* a, const unsigned* b) {
    asm volatile(
        "mma.sync.aligned.m16n8k16.row.col.f32.bf16.bf16.f32 "
        "{%0,%1,%2,%3}, {%4,%5,%6,%7}, {%8,%9}, {%0,%1,%2,%3};"
        : "+f"(c[0]), "+f"(c[1]), "+f"(c[2]), "+f"(c[3])
        : "r"(a[0]), "r"(a[1]), "r"(a[2]), "r"(a[3]), "r"(b[0]), "r"(b[1]));
}

// ---------------- weight split+transpose: W[K][Nc] -> Th/Tl[Nc][K] (bf16 hi/lo) ----
__global__ void wsplit_kernel(const float* __restrict__ W,
                              __nv_bfloat16* __restrict__ Th,
                              __nv_bfloat16* __restrict__ Tl, int K, int Nc)
{
    int idx = blockIdx.x * 256 + threadIdx.x;
    if (idx >= K * Nc) return;
    int k = idx / Nc, n = idx - k * Nc;
    float w = W[idx];
    __nv_bfloat16 h = __float2bfloat16_rn(w);
    float rem = w - __bfloat162float(h);
    Th[(size_t)n * K + k] = h;
    Tl[(size_t)n * K + k] = __float2bfloat16_rn(rem);
}

// ---------------- bf16x3 GEMM ----------------
// C[M,Nc] = op(A)[M,K] @ W[K,Nc] + bias, W given as transposed hi/lo bf16 [Nc][K].
//   preBN   : op(A)[,k] = gelu(g_sc[k]*A + g_sh[k])
//   statsOut: accumulate column sum/sumsq of C into g_colsum/g_colsqs
// CTA 128x128, BK=32, 256 threads (8 warps: 2M x 4N), warp tile 64x32.
__global__ __launch_bounds__(256)
void gemm_bf16x3_kernel(const float* __restrict__ A,
                        const __nv_bfloat16* __restrict__ Bhi,
                        const __nv_bfloat16* __restrict__ Blo,
                        const float* __restrict__ bias, float* __restrict__ C,
                        int M, int K, int Nc, int preBN, int statsOut)
{
    __shared__ unsigned short AsH[128][36];
    __shared__ unsigned short AsL[128][36];
    __shared__ unsigned short BsH[128][36];
    __shared__ unsigned short BsL[128][36];

    const int tid   = threadIdx.x;
    const int lane  = tid & 31, wid = tid >> 5;
    const int g     = lane >> 2, t4 = lane & 3;
    const int warpM = wid & 1,  warpN = wid >> 1;
    const int row0  = blockIdx.y * 128, col0 = blockIdx.x * 128;

    const int ldRow = tid >> 1;          // 0..127
    const int ldK   = (tid & 1) * 16;    // 0 or 16

    const bool aV = (row0 + ldRow) < M;
    const float* Aptr = A + (size_t)(row0 + ldRow) * K + ldK;
    const __nv_bfloat16* BhP = Bhi + (size_t)(col0 + ldRow) * K + ldK;
    const __nv_bfloat16* BlP = Blo + (size_t)(col0 + ldRow) * K + ldK;

    float acc[4][4][4];
    #pragma unroll
    for (int mi = 0; mi < 4; mi++)
        #pragma unroll
        for (int ni = 0; ni < 4; ni++)
            #pragma unroll
            for (int j = 0; j < 4; j++) acc[mi][ni][j] = 0.f;

    for (int k0 = 0; k0 < K; k0 += 32) {
        // ---- stage A: fp32 load (+preBN/GELU), split to bf16 hi/lo ----
        unsigned hP[8], lP[8];
        #pragma unroll
        for (int qv = 0; qv < 4; qv++) {
            float v[4] = {0.f, 0.f, 0.f, 0.f};
            if (aV) {
                float4 f = *(const float4*)(Aptr + k0 + qv * 4);
                v[0] = f.x; v[1] = f.y; v[2] = f.z; v[3] = f.w;
                if (preBN) {
                    const int kk = k0 + ldK + qv * 4;
                    #pragma unroll
                    for (int j = 0; j < 4; j++)
                        v[j] = gelu_exact(fmaf(g_sc[kk + j], v[j], g_sh[kk + j]));
                }
            }
            unsigned short hb[4], lb[4];
            #pragma unroll
            for (int j = 0; j < 4; j++) {
                __nv_bfloat16 h = __float2bfloat16_rn(v[j]);
                hb[j] = __bfloat16_as_ushort(h);
                lb[j] = __bfloat16_as_ushort(__float2bfloat16_rn(v[j] - __bfloat162float(h)));
            }
            hP[qv * 2 + 0] = (unsigned)hb[0] | ((unsigned)hb[1] << 16);
            hP[qv * 2 + 1] = (unsigned)hb[2] | ((unsigned)hb[3] << 16);
            lP[qv * 2 + 0] = (unsigned)lb[0] | ((unsigned)lb[1] << 16);
            lP[qv * 2 + 1] = (unsigned)lb[2] | ((unsigned)lb[3] << 16);
        }
        // ---- stage B: bf16 hi/lo direct copy ----
        uint4 bh0 = *(const uint4*)(BhP + k0);
        uint4 bh1 = *(const uint4*)(BhP + k0 + 8);
        uint4 bl0 = *(const uint4*)(BlP + k0);
        uint4 bl1 = *(const uint4*)(BlP + k0 + 8);

        __syncthreads();
        #pragma unroll
        for (int qv = 0; qv < 4; qv++) {
            *(uint2*)&AsH[ldRow][ldK + qv * 4] = make_uint2(hP[qv * 2], hP[qv * 2 + 1]);
            *(uint2*)&AsL[ldRow][ldK + qv * 4] = make_uint2(lP[qv * 2], lP[qv * 2 + 1]);
        }
        *(uint2*)&BsH[ldRow][ldK + 0]  = make_uint2(bh0.x, bh0.y);
        *(uint2*)&BsH[ldRow][ldK + 4]  = make_uint2(bh0.z, bh0.w);
        *(uint2*)&BsH[ldRow][ldK + 8]  = make_uint2(bh1.x, bh1.y);
        *(uint2*)&BsH[ldRow][ldK + 12] = make_uint2(bh1.z, bh1.w);
        *(uint2*)&BsL[ldRow][ldK + 0]  = make_uint2(bl0.x, bl0.y);
        *(uint2*)&BsL[ldRow][ldK + 4]  = make_uint2(bl0.z, bl0.w);
        *(uint2*)&BsL[ldRow][ldK + 8]  = make_uint2(bl1.x, bl1.y);
        *(uint2*)&BsL[ldRow][ldK + 12] = make_uint2(bl1.z, bl1.w);
        __syncthreads();

        // ---- two k16 MMA steps ----
        #pragma unroll
        for (int s = 0; s < 2; s++) {
            const int ks = s * 16;
            unsigned bH[4][2], bL[4][2];
            #pragma unroll
            for (int ni = 0; ni < 4; ni++) {
                int n = warpN * 32 + ni * 8 + g;
                bH[ni][0] = *(const unsigned*)&BsH[n][ks + t4 * 2];
                bH[ni][1] = *(const unsigned*)&BsH[n][ks + t4 * 2 + 8];
                bL[ni][0] = *(const unsigned*)&BsL[n][ks + t4 * 2];
                bL[ni][1] = *(const unsigned*)&BsL[n][ks + t4 * 2 + 8];
            }
            #pragma unroll
            for (int mi = 0; mi < 4; mi++) {
                int m = warpM * 64 + mi * 16 + g;
                unsigned aH[4], aL[4];
                aH[0] = *(const unsigned*)&AsH[m][ks + t4 * 2];
                aH[1] = *(const unsigned*)&AsH[m + 8][ks + t4 * 2];
                aH[2] = *(const unsigned*)&AsH[m][ks + t4 * 2 + 8];
                aH[3] = *(const unsigned*)&AsH[m + 8][ks + t4 * 2 + 8];
                aL[0] = *(const unsigned*)&AsL[m][ks + t4 * 2];
                aL[1] = *(const unsigned*)&AsL[m + 8][ks + t4 * 2];
                aL[2] = *(const unsigned*)&AsL[m][ks + t4 * 2 + 8];
                aL[3] = *(const unsigned*)&AsL[m + 8][ks + t4 * 2 + 8];
                #pragma unroll
                for (int ni = 0; ni < 4; ni++) {
                    mma_bf16(acc[mi][ni], aH, bH[ni]);
                    mma_bf16(acc[mi][ni], aH, bL[ni]);
                    mma_bf16(acc[mi][ni], aL, bH[ni]);
                }
            }
        }
    }

    // ---- epilogue: bias, store, fused column stats ----
    float bv[4][2];
    #pragma unroll
    for (int ni = 0; ni < 4; ni++) {
        float2 b2 = *(const float2*)(bias + col0 + warpN * 32 + ni * 8 + t4 * 2);
        bv[ni][0] = b2.x; bv[ni][1] = b2.y;
    }
    float sP[4][2], qP[4][2];
    #pragma unroll
    for (int ni = 0; ni < 4; ni++)
        #pragma unroll
        for (int j = 0; j < 2; j++) { sP[ni][j] = 0.f; qP[ni][j] = 0.f; }

    #pragma unroll
    for (int mi = 0; mi < 4; mi++) {
        int r0 = row0 + warpM * 64 + mi * 16 + g;
        int r1 = r0 + 8;
        bool v0 = r0 < M, v1 = r1 < M;
        #pragma unroll
        for (int ni = 0; ni < 4; ni++) {
            int c = col0 + warpN * 32 + ni * 8 + t4 * 2;
            float o0 = acc[mi][ni][0] + bv[ni][0];
            float o1 = acc[mi][ni][1] + bv[ni][1];
            float o2 = acc[mi][ni][2] + bv[ni][0];
            float o3 = acc[mi][ni][3] + bv[ni][1];
            if (v0) {
                *(float2*)(C + (size_t)r0 * Nc + c) = make_float2(o0, o1);
                sP[ni][0] += o0; qP[ni][0] += o0 * o0;
                sP[ni][1] += o1; qP[ni][1] += o1 * o1;
            }
            if (v1) {
                *(float2*)(C + (size_t)r1 * Nc + c) = make_float2(o2, o3);
                sP[ni][0] += o2; qP[ni][0] += o2 * o2;
                sP[ni][1] += o3; qP[ni][1] += o3 * o3;
            }
        }
    }
    if (statsOut) {
        #pragma unroll
        for (int off = 16; off >= 4; off >>= 1) {
            #pragma unroll
            for (int ni = 0; ni < 4; ni++)
                #pragma unroll
                for (int j = 0; j < 2; j++) {
                    sP[ni][j] += __shfl_down_sync(0xffffffffu, sP[ni][j], off);
                    qP[ni][j] += __shfl_down_sync(0xffffffffu, qP[ni][j], off);
                }
        }
        if (lane < 4) {
            #pragma unroll
            for (int ni = 0; ni < 4; ni++)
                #pragma unroll
                for (int j = 0; j < 2; j++) {
                    int c = col0 + warpN * 32 + ni * 8 + lane * 2 + j;
                    atomicAdd(&g_colsum[c], sP[ni][j]);
                    atomicAdd(&g_colsqs[c], qP[ni][j]);
                }
        }
    }
}

// ---------------- finalize: fold BN params, re-zero accumulators ----------------
__global__ void bn_finalize_kernel(int M, int Nc,
                                   const float* __restrict__ gamma,
                                   const float* __restrict__ beta)
{
    int c = threadIdx.x;
    if (c < Nc) {
        float s = g_colsum[c], q = g_colsqs[c];
        float m = s / (float)M;
        float v = q / (float)M - m * m;
        float rs = rsqrtf(v + 1e-5f);
        float sc = gamma[c] * rs;
        g_sc[c] = sc;
        g_sh[c] = beta[c] - m * sc;
    }
    g_colsum[c] = 0.f;
    g_colsqs[c] = 0.f;
}

// ---------------- standalone BN apply (+ residuals, dual output) ----------------
__global__ void bn_apply_kernel(const float* __restrict__ Z,
                                const float* __restrict__ r1,
                                const float* __restrict__ r2,
                                float* __restrict__ out,
                                float* __restrict__ out2,
                                int M, int Nc)
{
    size_t idx = ((size_t)blockIdx.x * blockDim.x + threadIdx.x) * 4;
    if (idx >= (size_t)M * Nc) return;
    int c = (int)(idx % (size_t)Nc);

    float4 z = *(const float4*)(Z + idx);
    float o[4] = {
        fmaf(g_sc[c + 0], z.x, g_sh[c + 0]),
        fmaf(g_sc[c + 1], z.y, g_sh[c + 1]),
        fmaf(g_sc[c + 2], z.z, g_sh[c + 2]),
        fmaf(g_sc[c + 3], z.w, g_sh[c + 3])
    };
    if (r1) {
        float4 a = *(const float4*)(r1 + idx);
        o[0] += a.x; o[1] += a.y; o[2] += a.z; o[3] += a.w;
    }
    if (r2) {
        float4 a = *(const float4*)(r2 + idx);
        o[0] += a.x; o[1] += a.y; o[2] += a.z; o[3] += a.w;
    }
    float4 ov = make_float4(o[0], o[1], o[2], o[3]);
    *(float4*)(out + idx) = ov;
    if (out2) *(float4*)(out2 + idx) = ov;
}

// ---------------- edge scatter-add: agg[dst] += h0[src] ----------------
__global__ void scatter_add_kernel(const float* __restrict__ H,
                                   const int* __restrict__ src,
                                   const int* __restrict__ dst,
                                   float* __restrict__ agg, int E)
{
    int e = blockIdx.x * 8 + threadIdx.y;
    if (e >= E) return;
    int s = src[e], d = dst[e];
    const float* hs = H + (size_t)s * DIM;
    float* ad = agg + (size_t)d * DIM;
    int l = threadIdx.x;
    #pragma unroll
    for (int j = 0; j < 4; j++) {
        atomicAdd(ad + l + j * 32, __ldg(hs + l + j * 32));
    }
}

// ---------------- host orchestration ----------------
extern "C" void kernel_launch(void* const* d_in, const int* in_sizes, int n_in,
                              void* d_out, int out_size)
{
    const float* x     = (const float*)d_in[0];
    const int*   ei    = (const int*)  d_in[1];
    const float* encW  = (const float*)d_in[2];
    const float* encb  = (const float*)d_in[3];
    const float* bng   = (const float*)d_in[4];
    const float* bnb   = (const float*)d_in[5];
    const float* gW1   = (const float*)d_in[6];
    const float* gb1   = (const float*)d_in[7];
    const float* gg    = (const float*)d_in[8];
    const float* gbb   = (const float*)d_in[9];
    const float* gW2   = (const float*)d_in[10];
    const float* gb2   = (const float*)d_in[11];
    const float* f2W1  = (const float*)d_in[12];
    const float* f2b1  = (const float*)d_in[13];
    const float* f2g1  = (const float*)d_in[14];
    const float* f2bb1 = (const float*)d_in[15];
    const float* f2W2  = (const float*)d_in[16];
    const float* f2b2  = (const float*)d_in[17];
    const float* f2g2  = (const float*)d_in[18];
    const float* f2bb2 = (const float*)d_in[19];
    const float* fnW1  = (const float*)d_in[20];
    const float* fnb1  = (const float*)d_in[21];
    const float* fng1  = (const float*)d_in[22];
    const float* fnbb1 = (const float*)d_in[23];
    const float* fnW2  = (const float*)d_in[24];
    const float* fnb2  = (const float*)d_in[25];
    const float* fng2  = (const float*)d_in[26];
    const float* fnbb2 = (const float*)d_in[27];

    const int M = in_sizes[0] / DIM;
    const int E = in_sizes[1] / 2;

    float *Z, *T, *h0, *agg, *h1, *h4;
    __nv_bfloat16 *Wh, *Wl;
    cudaGetSymbolAddress((void**)&Z,   g_Z);
    cudaGetSymbolAddress((void**)&T,   g_T);
    cudaGetSymbolAddress((void**)&h0,  g_h0);
    cudaGetSymbolAddress((void**)&agg, g_agg);
    cudaGetSymbolAddress((void**)&h1,  g_h1);
    cudaGetSymbolAddress((void**)&h4,  g_h4);
    cudaGetSymbolAddress((void**)&Wh,  g_Wh);
    cudaGetSymbolAddress((void**)&Wl,  g_Wl);

    // weight scratch offsets (elements)
    const size_t oEnc = 0, oG1 = 16384, oG2 = 32768, oF21 = 49152,
                 oF22 = 81920, oFN1 = 114688, oFN2 = 180224;

    auto wsplit = [&](const float* W, size_t off, int K, int Nc) {
        int tot = K * Nc;
        wsplit_kernel<<<(tot + 255) / 256, 256>>>(W, Wh + off, Wl + off, K, Nc);
    };
    const int gy = (M + 127) / 128;
    auto gemm = [&](const float* A, size_t woff, const float* b, float* C,
                    int K, int Nc, int preBN, int statsOut) {
        dim3 grid(Nc / 128, gy);
        gemm_bf16x3_kernel<<<grid, 256>>>(A, Wh + woff, Wl + woff, b, C,
                                          M, K, Nc, preBN, statsOut);
    };
    auto finalize = [&](int Nc, const float* ga, const float* be) {
        bn_finalize_kernel<<<1, 512>>>(M, Nc, ga, be);
    };
    auto bn = [&](const float* Zp, const float* r1, const float* r2,
                  float* o, float* o2, int Nc) {
        size_t tot = (size_t)M * Nc / 4;
        bn_apply_kernel<<<(unsigned)((tot + 255) / 256), 256>>>(Zp, r1, r2, o, o2, M, Nc);
    };

    // 0) weight splits + zero stats accumulators
    wsplit(encW, oEnc, DIM, DIM);
    wsplit(gW1,  oG1,  DIM, DIM);
    wsplit(gW2,  oG2,  DIM, DIM);
    wsplit(f2W1, oF21, DIM, 2 * DIM);
    wsplit(f2W2, oF22, 2 * DIM, DIM);
    wsplit(fnW1, oFN1, DIM, 4 * DIM);
    wsplit(fnW2, oFN2, 4 * DIM, DIM);
    finalize(0, encb, encb);

    // 1) Z = x @ encW + encb (stats) -> h0 = BN(Z), agg = h0
    gemm(x, oEnc, encb, Z, DIM, DIM, 0, 1);
    finalize(DIM, bng, bnb);
    bn(Z, nullptr, nullptr, h0, agg, DIM);

    // 2) agg[dst] += h0[src]
    {
        dim3 blk(32, 8);
        scatter_add_kernel<<<(E + 7) / 8, blk>>>(h0, ei, ei + E, agg, E);
    }

    // 3) GIN MLP
    gemm(agg, oG1, gb1, Z, DIM, DIM, 0, 1);
    finalize(DIM, gg, gbb);
    gemm(Z, oG2, gb2, h1, DIM, DIM, 1, 0);

    // 4) fc2 FFN + residuals
    gemm(h1, oF21, f2b1, Z, DIM, 2 * DIM, 0, 1);
    finalize(2 * DIM, f2g1, f2bb1);
    gemm(Z, oF22, f2b2, T, 2 * DIM, DIM, 1, 1);
    finalize(DIM, f2g2, f2bb2);
    bn(T, h1, x, h4, nullptr, DIM);           // h4 = BN(T) + h1 + x

    // 5) final FFN
    gemm(h4, oFN1, fnb1, Z, DIM, 4 * DIM, 0, 1);
    finalize(4 * DIM, fng1, fnbb1);
    gemm(Z, oFN2, fnb2, T, 4 * DIM, DIM, 1, 1);
    finalize(DIM, fng2, fnbb2);
    bn(T, h4, nullptr, (float*)d_out, nullptr, DIM);  // out = BN(T) + h4
}